// round 11
// baseline (speedup 1.0000x reference)
#include <cuda_runtime.h>
#include <cstdint>
#include <cstddef>

// Problem dims
#define T_LEN 4096
#define HD    512
#define G3    1536          // 3*HD
#define NC    4880

// ---------------- scratch (static device memory; no allocations) -------------
__device__ float g_visit[(size_t)T_LEN * HD];        // 8 MB
__device__ float g_gi[(size_t)T_LEN * G3];           // 25 MB
__device__ float g_hs[(size_t)T_LEN * HD];           // 8 MB
__device__ float g_logits[T_LEN];
__device__ float g_part[32 * HD];

// ---------------- f32x2 packed math (sm_100+) --------------------------------
#define FMA2(d, a, b, c) \
    asm("fma.rn.f32x2 %0, %1, %2, %3;" : "=l"(d) : "l"(a), "l"(b), "l"(c))
#define PACK2(d, lo, hi) \
    asm("mov.b64 %0, {%1, %2};" : "=l"(d) : "f"(lo), "f"(hi))
#define UNPACK2(lo, hi, d) \
    asm("mov.b64 {%0, %1}, %2;" : "=f"(lo), "=f"(hi) : "l"(d))

// MUFU-only sigmoid / tanh (ex2.approx + rcp.approx, ~2ulp each)
__device__ __forceinline__ float fast_sigmoid(float x) {
    float e, r;
    asm("ex2.approx.f32 %0, %1;" : "=f"(e) : "f"(-1.4426950408889634f * x));
    asm("rcp.approx.f32 %0, %1;" : "=f"(r) : "f"(1.0f + e));
    return r;
}
__device__ __forceinline__ float fast_tanh(float x) {
    float e, r;
    asm("ex2.approx.f32 %0, %1;" : "=f"(e) : "f"(2.8853900817779268f * x));
    asm("rcp.approx.f32 %0, %1;" : "=f"(r) : "f"(1.0f + e));
    return fmaf(-2.0f, r, 1.0f);
}

// =============================================================================
// GEMM 1: g_visit[t, d] = sum_c H[c, t] * X[c, d]
// =============================================================================
__global__ __launch_bounds__(256) void gemm_visit(const float* __restrict__ Hm,
                                                  const float* __restrict__ X) {
    __shared__ float As[8][128];
    __shared__ float Bs[8][128];
    const int tid = threadIdx.x;
    const int m0 = blockIdx.y * 128;
    const int n0 = blockIdx.x * 128;
    const int tx = tid & 15, ty = tid >> 4;
    const int lk = tid >> 5;            // 0..7
    const int lm = (tid & 31) * 4;      // 0..124

    unsigned long long acc[8][4];
#pragma unroll
    for (int i = 0; i < 8; i++)
#pragma unroll
        for (int j = 0; j < 4; j++) acc[i][j] = 0ull;

    for (int k0 = 0; k0 < NC; k0 += 8) {
        *(float4*)&As[lk][lm] = *(const float4*)&Hm[(size_t)(k0 + lk) * T_LEN + m0 + lm];
        *(float4*)&Bs[lk][lm] = *(const float4*)&X[(size_t)(k0 + lk) * HD + n0 + lm];
        __syncthreads();
#pragma unroll
        for (int kt = 0; kt < 8; kt++) {
            float a[8];
            unsigned long long b2[4];
#pragma unroll
            for (int i = 0; i < 8; i++) a[i] = As[kt][ty * 8 + i];
#pragma unroll
            for (int j = 0; j < 4; j++)
                b2[j] = *(const unsigned long long*)&Bs[kt][tx * 8 + 2 * j];
#pragma unroll
            for (int i = 0; i < 8; i++) {
                unsigned long long ad;
                PACK2(ad, a[i], a[i]);
#pragma unroll
                for (int j = 0; j < 4; j++) FMA2(acc[i][j], ad, b2[j], acc[i][j]);
            }
        }
        __syncthreads();
    }
#pragma unroll
    for (int i = 0; i < 8; i++)
#pragma unroll
        for (int j = 0; j < 4; j++) {
            float lo, hi;
            UNPACK2(lo, hi, acc[i][j]);
            size_t base = (size_t)(m0 + ty * 8 + i) * HD + n0 + tx * 8 + 2 * j;
            g_visit[base] = lo;
            g_visit[base + 1] = hi;
        }
}

// =============================================================================
// GEMM 2: g_gi[t, r] = sum_d g_visit[t, d] * W_ih[r, d] + b_ih[r]
// =============================================================================
__global__ __launch_bounds__(256) void gemm_gi(const float* __restrict__ Wih,
                                               const float* __restrict__ bih) {
    __shared__ float As[8][128];
    __shared__ float Bs[8][128];
    const int tid = threadIdx.x;
    const int m0 = blockIdx.y * 128;
    const int n0 = blockIdx.x * 128;
    const int tx = tid & 15, ty = tid >> 4;
    const int lrow = tid >> 1;          // 0..127
    const int q0 = (tid & 1) * 4;       // 0 or 4

    unsigned long long acc[8][4];
#pragma unroll
    for (int i = 0; i < 8; i++)
#pragma unroll
        for (int j = 0; j < 4; j++) acc[i][j] = 0ull;

    for (int k0 = 0; k0 < HD; k0 += 8) {
        float4 va = *(const float4*)&g_visit[(size_t)(m0 + lrow) * HD + k0 + q0];
        float4 vb = *(const float4*)&Wih[(size_t)(n0 + lrow) * HD + k0 + q0];
        As[q0 + 0][lrow] = va.x; As[q0 + 1][lrow] = va.y;
        As[q0 + 2][lrow] = va.z; As[q0 + 3][lrow] = va.w;
        Bs[q0 + 0][lrow] = vb.x; Bs[q0 + 1][lrow] = vb.y;
        Bs[q0 + 2][lrow] = vb.z; Bs[q0 + 3][lrow] = vb.w;
        __syncthreads();
#pragma unroll
        for (int kt = 0; kt < 8; kt++) {
            float a[8];
            unsigned long long b2[4];
#pragma unroll
            for (int i = 0; i < 8; i++) a[i] = As[kt][ty * 8 + i];
#pragma unroll
            for (int j = 0; j < 4; j++)
                b2[j] = *(const unsigned long long*)&Bs[kt][tx * 8 + 2 * j];
#pragma unroll
            for (int i = 0; i < 8; i++) {
                unsigned long long ad;
                PACK2(ad, a[i], a[i]);
#pragma unroll
                for (int j = 0; j < 4; j++) FMA2(acc[i][j], ad, b2[j], acc[i][j]);
            }
        }
        __syncthreads();
    }
#pragma unroll
    for (int i = 0; i < 8; i++)
#pragma unroll
        for (int j = 0; j < 4; j++) {
            float lo, hi;
            UNPACK2(lo, hi, acc[i][j]);
            int n = n0 + tx * 8 + 2 * j;
            size_t base = (size_t)(m0 + ty * 8 + i) * G3 + n;
            g_gi[base] = lo + bih[n];
            g_gi[base + 1] = hi + bih[n + 1];
        }
}

// =============================================================================
// GRU scan: 16-CTA cluster, 512 threads/CTA, persistent over 4096 steps.
//   Proven-safe sync: plain st.shared::cluster + SPLIT barrier.cluster
//   (arrive right after stores = release; wait at loop top = acquire).
//   De-serialized step:
//     * warp w owns dims {2w, 2w+1}; its 6 W_hh rows are r/z/n for them.
//     * after the warp's own butterfly reductions, ALL lanes hold the 6 sums
//       -> lane l computes gates for dim 2w+(l&1) and stores h_new to CTA
//       (l>>1) at GLOBAL offset dim_g = rank*32 + 2w + (l&1).
//       (R9 bug: stored at local offset dim_l -> only slots 0..31 written.)
//     * h_old kept in registers (identical value in all 16 lanes of a dim).
//     * gi(t+1) prefetched in the arrive->wait shadow.
//   Double-buffer invariant: stores at step t target buffer p^1; reads of p
//   at step t all precede arrive(t); producers' next stores to p occur after
//   wait(t+1).  No race.
// =============================================================================
__global__ __launch_bounds__(512, 1) void k_gru(const float* __restrict__ Whh,
                                                const float* __restrict__ bhh) {
    __shared__ float h_buf[2][HD];
    const int tid = threadIdx.x;
    const int warp = tid >> 5, lane = tid & 31;
    const int q = lane & 1;            // which of the warp's 2 dims
    const int dstc = lane >> 1;        // destination CTA rank (0..15)
    unsigned int rank;
    asm("mov.u32 %0, %%cluster_ctarank;" : "=r"(rank));

    for (int i = tid; i < 2 * HD; i += 512) ((float*)h_buf)[i] = 0.f;

    const int dim_l = 2 * warp + q;                  // local dim 0..31
    const int dim_g = (int)rank * 32 + dim_l;        // global dim 0..511

    // Register-resident weights, stride-32 k-permutation:
    // pair i = (k = lane+64i, k = lane+64i+32).
    // r = 0..5 -> gate (r>>1) in {r,z,n}, sub-dim (r&1).
    unsigned long long Wr[6][8];
#pragma unroll
    for (int r = 0; r < 6; r++) {
        const int grow = (r >> 1) * HD + (int)rank * 32 + 2 * warp + (r & 1);
        const float* wp = Whh + (size_t)grow * HD;
#pragma unroll
        for (int i = 0; i < 8; i++) {
            float wlo = wp[lane + 64 * i];
            float whi = wp[lane + 64 * i + 32];
            PACK2(Wr[r][i], wlo, whi);
        }
    }

    // biases for this lane's dim
    const float bh_r = bhh[dim_g];
    const float bh_z = bhh[HD + dim_g];
    const float bh_n = bhh[2 * HD + dim_g];
    float h_reg = 0.f;                 // h_old for this lane's dim

    unsigned int hbase;
    asm("{ .reg .u64 t; cvta.to.shared.u64 t, %1; cvt.u32.u64 %0, t; }"
        : "=r"(hbase) : "l"(&h_buf[0][0]));

    // gi(0) prefetch
    const float* gbase = g_gi + dim_g;
    float gi_r = __ldg(gbase);
    float gi_z = __ldg(gbase + HD);
    float gi_n = __ldg(gbase + 2 * HD);

    __syncthreads();
    asm volatile("barrier.cluster.arrive.aligned;" ::: "memory");

    int p = 0;
    for (int t = 0; t < T_LEN; t++) {
        // acquire h(t): pairs with everyone's arrive from step t-1 (or init)
        asm volatile("barrier.cluster.wait.aligned;" ::: "memory");

        // --- FMA phase: 6 row-partials from register weights x smem h(t) ---
        unsigned long long acc[6];
#pragma unroll
        for (int r = 0; r < 6; r++) acc[r] = 0ull;
        const float* hp = &h_buf[p][lane];
#pragma unroll
        for (int i = 0; i < 8; i++) {
            float hlo = hp[64 * i];        // bank = lane (conflict-free)
            float hhi = hp[64 * i + 32];
            unsigned long long h2;
            PACK2(h2, hlo, hhi);
#pragma unroll
            for (int r = 0; r < 6; r++) FMA2(acc[r], Wr[r][i], h2, acc[r]);
        }

        // --- full butterfly per row: every lane ends with all 6 sums ---
        float s[6];
#pragma unroll
        for (int r = 0; r < 6; r++) {
            float lo, hi;
            UNPACK2(lo, hi, acc[r]);
            float v = lo + hi;
#pragma unroll
            for (int off = 16; off; off >>= 1)
                v += __shfl_xor_sync(0xffffffffu, v, off);
            s[r] = v;
        }

        // --- gates for this lane's dim (identical in all 16 lanes of a dim) ---
        float xr = s[q]     + gi_r + bh_r;
        float xz = s[2 + q] + gi_z + bh_z;
        float dn = s[4 + q];
        float rr = fast_sigmoid(xr);
        float zz = fast_sigmoid(xz);
        float nn = fast_tanh(gi_n + rr * (dn + bh_n));
        h_reg = (1.f - zz) * nn + zz * h_reg;

        // --- one DSMEM store per lane: GLOBAL dim slot -> CTA dstc, buf p^1 ---
        {
            unsigned int dst = hbase + 4u * (unsigned)((p ^ 1) * HD + dim_g);
            unsigned int rem;
            asm("mapa.shared::cluster.u32 %0, %1, %2;"
                : "=r"(rem) : "r"(dst), "r"(dstc));
            asm volatile("st.shared::cluster.f32 [%0], %1;"
                         :: "r"(rem), "f"(h_reg) : "memory");
        }
        // release our stores for step t
        asm volatile("barrier.cluster.arrive.aligned;" ::: "memory");

        // --- shadow work (overlaps peers reaching the barrier) ---
        if (dstc == 0)                 // one lane per dim writes history
            g_hs[(size_t)t * HD + dim_g] = h_reg;
        {
            const int tn = (t + 1 < T_LEN) ? t + 1 : t;   // in-bounds prefetch
            const float* gp = gbase + (size_t)tn * G3;
            gi_r = __ldg(gp);
            gi_z = __ldg(gp + HD);
            gi_n = __ldg(gp + 2 * HD);
        }
        p ^= 1;
    }
    // final pairing wait: also guarantees no CTA exits while peers could
    // still address its smem
    asm volatile("barrier.cluster.wait.aligned;" ::: "memory");
}

// =============================================================================
// Attention epilogue
// =============================================================================
__global__ void k_logits(const float* __restrict__ watt) {
    const int t = blockIdx.x * 8 + (threadIdx.x >> 5);
    const int lane = threadIdx.x & 31;
    float s = 0.f;
#pragma unroll
    for (int i = 0; i < 16; i++)
        s += g_hs[(size_t)t * HD + lane + 32 * i] * watt[lane + 32 * i];
#pragma unroll
    for (int off = 16; off; off >>= 1) s += __shfl_xor_sync(0xffffffffu, s, off);
    if (lane == 0) g_logits[t] = s;
}

__global__ void k_softmax() {
    __shared__ float red[32];
    __shared__ float bcast;
    const int tid = threadIdx.x, lane = tid & 31, w = tid >> 5;
    float v[4], m = -1e30f;
#pragma unroll
    for (int i = 0; i < 4; i++) {
        v[i] = g_logits[tid + 1024 * i];
        m = fmaxf(m, v[i]);
    }
#pragma unroll
    for (int off = 16; off; off >>= 1)
        m = fmaxf(m, __shfl_xor_sync(0xffffffffu, m, off));
    if (lane == 0) red[w] = m;
    __syncthreads();
    if (w == 0) {
        float x = red[lane];
#pragma unroll
        for (int off = 16; off; off >>= 1)
            x = fmaxf(x, __shfl_xor_sync(0xffffffffu, x, off));
        if (lane == 0) bcast = x;
    }
    __syncthreads();
    const float M = bcast;
    __syncthreads();
    float s = 0.f;
#pragma unroll
    for (int i = 0; i < 4; i++) {
        v[i] = __expf(v[i] - M);
        s += v[i];
    }
#pragma unroll
    for (int off = 16; off; off >>= 1) s += __shfl_xor_sync(0xffffffffu, s, off);
    if (lane == 0) red[w] = s;
    __syncthreads();
    if (w == 0) {
        float x = red[lane];
#pragma unroll
        for (int off = 16; off; off >>= 1) x += __shfl_xor_sync(0xffffffffu, x, off);
        if (lane == 0) bcast = 1.f / x;
    }
    __syncthreads();
    const float inv = bcast;
#pragma unroll
    for (int i = 0; i < 4; i++) g_logits[tid + 1024 * i] = v[i] * inv;
}

__global__ void k_wsum() {
    const int d = threadIdx.x;
    const int b = blockIdx.x;
    float acc = 0.f;
    for (int t = b * 128; t < b * 128 + 128; t++)
        acc += g_logits[t] * g_hs[(size_t)t * HD + d];
    g_part[b * HD + d] = acc;
}

__global__ void k_final(float* __restrict__ out) {
    const int d = threadIdx.x;
    float acc = 0.f;
#pragma unroll
    for (int b = 0; b < 32; b++) acc += g_part[b * HD + d];
    out[d] = acc;
}

// =============================================================================
// Launch
// =============================================================================
extern "C" void kernel_launch(void* const* d_in, const int* in_sizes, int n_in,
                              void* d_out, int out_size) {
    const float* H    = (const float*)d_in[0];
    // d_in[1] = TE (unused)
    const float* Xemb = (const float*)d_in[2];
    const float* Wih  = (const float*)d_in[3];
    const float* Whh  = (const float*)d_in[4];
    const float* bih  = (const float*)d_in[5];
    const float* bhh  = (const float*)d_in[6];
    const float* watt = (const float*)d_in[7];
    float* out = (float*)d_out;

    gemm_visit<<<dim3(4, 32), 256>>>(H, Xemb);
    gemm_gi<<<dim3(12, 32), 256>>>(Wih, bih);

    // 16-CTA cluster GRU scan
    cudaFuncSetAttribute(k_gru, cudaFuncAttributeNonPortableClusterSizeAllowed, 1);
    cudaLaunchConfig_t cfg = {};
    cfg.gridDim = dim3(16, 1, 1);
    cfg.blockDim = dim3(512, 1, 1);
    cfg.dynamicSmemBytes = 0;
    cfg.stream = 0;
    cudaLaunchAttribute attrs[1];
    attrs[0].id = cudaLaunchAttributeClusterDimension;
    attrs[0].val.clusterDim.x = 16;
    attrs[0].val.clusterDim.y = 1;
    attrs[0].val.clusterDim.z = 1;
    cfg.attrs = attrs;
    cfg.numAttrs = 1;
    cudaLaunchKernelEx(&cfg, k_gru, Whh, bhh);

    k_logits<<<512, 256>>>(watt);
    k_softmax<<<1, 1024>>>();
    k_wsum<<<32, 512>>>();
    k_final<<<1, 512>>>(out);
}

// round 17
// speedup vs baseline: 1.0289x; 1.0289x over previous
#include <cuda_runtime.h>
#include <cstdint>
#include <cstddef>

// Problem dims
#define T_LEN 4096
#define HD    512
#define G3    1536          // 3*HD
#define NC    4880
#define HPAD  640           // padded permuted h buffer (stride 20 floats/lane)

// ---------------- scratch (static device memory; no allocations) -------------
__device__ float g_visit[(size_t)T_LEN * HD];        // 8 MB
__device__ float g_gi[(size_t)T_LEN * G3];           // 25 MB
__device__ float g_hs[(size_t)T_LEN * HD];           // 8 MB
__device__ float g_logits[T_LEN];
__device__ float g_part[32 * HD];

// ---------------- f32x2 packed math (sm_100+) --------------------------------
#define FMA2(d, a, b, c) \
    asm("fma.rn.f32x2 %0, %1, %2, %3;" : "=l"(d) : "l"(a), "l"(b), "l"(c))
#define PACK2(d, lo, hi) \
    asm("mov.b64 %0, {%1, %2};" : "=l"(d) : "f"(lo), "f"(hi))
#define UNPACK2(lo, hi, d) \
    asm("mov.b64 {%0, %1}, %2;" : "=f"(lo), "=f"(hi) : "l"(d))

// MUFU-only sigmoid / tanh (ex2.approx + rcp.approx, ~2ulp each)
__device__ __forceinline__ float fast_sigmoid(float x) {
    float e, r;
    asm("ex2.approx.f32 %0, %1;" : "=f"(e) : "f"(-1.4426950408889634f * x));
    asm("rcp.approx.f32 %0, %1;" : "=f"(r) : "f"(1.0f + e));
    return r;
}
__device__ __forceinline__ float fast_tanh(float x) {
    float e, r;
    asm("ex2.approx.f32 %0, %1;" : "=f"(e) : "f"(2.8853900817779268f * x));
    asm("rcp.approx.f32 %0, %1;" : "=f"(r) : "f"(1.0f + e));
    return fmaf(-2.0f, r, 1.0f);
}

// =============================================================================
// GEMM 1: g_visit[t, d] = sum_c H[c, t] * X[c, d]
// =============================================================================
__global__ __launch_bounds__(256) void gemm_visit(const float* __restrict__ Hm,
                                                  const float* __restrict__ X) {
    __shared__ float As[8][128];
    __shared__ float Bs[8][128];
    const int tid = threadIdx.x;
    const int m0 = blockIdx.y * 128;
    const int n0 = blockIdx.x * 128;
    const int tx = tid & 15, ty = tid >> 4;
    const int lk = tid >> 5;            // 0..7
    const int lm = (tid & 31) * 4;      // 0..124

    unsigned long long acc[8][4];
#pragma unroll
    for (int i = 0; i < 8; i++)
#pragma unroll
        for (int j = 0; j < 4; j++) acc[i][j] = 0ull;

    for (int k0 = 0; k0 < NC; k0 += 8) {
        *(float4*)&As[lk][lm] = *(const float4*)&Hm[(size_t)(k0 + lk) * T_LEN + m0 + lm];
        *(float4*)&Bs[lk][lm] = *(const float4*)&X[(size_t)(k0 + lk) * HD + n0 + lm];
        __syncthreads();
#pragma unroll
        for (int kt = 0; kt < 8; kt++) {
            float a[8];
            unsigned long long b2[4];
#pragma unroll
            for (int i = 0; i < 8; i++) a[i] = As[kt][ty * 8 + i];
#pragma unroll
            for (int j = 0; j < 4; j++)
                b2[j] = *(const unsigned long long*)&Bs[kt][tx * 8 + 2 * j];
#pragma unroll
            for (int i = 0; i < 8; i++) {
                unsigned long long ad;
                PACK2(ad, a[i], a[i]);
#pragma unroll
                for (int j = 0; j < 4; j++) FMA2(acc[i][j], ad, b2[j], acc[i][j]);
            }
        }
        __syncthreads();
    }
#pragma unroll
    for (int i = 0; i < 8; i++)
#pragma unroll
        for (int j = 0; j < 4; j++) {
            float lo, hi;
            UNPACK2(lo, hi, acc[i][j]);
            size_t base = (size_t)(m0 + ty * 8 + i) * HD + n0 + tx * 8 + 2 * j;
            g_visit[base] = lo;
            g_visit[base + 1] = hi;
        }
}

// =============================================================================
// GEMM 2: g_gi[t, r] = sum_d g_visit[t, d] * W_ih[r, d] + b_ih[r]
// =============================================================================
__global__ __launch_bounds__(256) void gemm_gi(const float* __restrict__ Wih,
                                               const float* __restrict__ bih) {
    __shared__ float As[8][128];
    __shared__ float Bs[8][128];
    const int tid = threadIdx.x;
    const int m0 = blockIdx.y * 128;
    const int n0 = blockIdx.x * 128;
    const int tx = tid & 15, ty = tid >> 4;
    const int lrow = tid >> 1;          // 0..127
    const int q0 = (tid & 1) * 4;       // 0 or 4

    unsigned long long acc[8][4];
#pragma unroll
    for (int i = 0; i < 8; i++)
#pragma unroll
        for (int j = 0; j < 4; j++) acc[i][j] = 0ull;

    for (int k0 = 0; k0 < HD; k0 += 8) {
        float4 va = *(const float4*)&g_visit[(size_t)(m0 + lrow) * HD + k0 + q0];
        float4 vb = *(const float4*)&Wih[(size_t)(n0 + lrow) * HD + k0 + q0];
        As[q0 + 0][lrow] = va.x; As[q0 + 1][lrow] = va.y;
        As[q0 + 2][lrow] = va.z; As[q0 + 3][lrow] = va.w;
        Bs[q0 + 0][lrow] = vb.x; Bs[q0 + 1][lrow] = vb.y;
        Bs[q0 + 2][lrow] = vb.z; Bs[q0 + 3][lrow] = vb.w;
        __syncthreads();
#pragma unroll
        for (int kt = 0; kt < 8; kt++) {
            float a[8];
            unsigned long long b2[4];
#pragma unroll
            for (int i = 0; i < 8; i++) a[i] = As[kt][ty * 8 + i];
#pragma unroll
            for (int j = 0; j < 4; j++)
                b2[j] = *(const unsigned long long*)&Bs[kt][tx * 8 + 2 * j];
#pragma unroll
            for (int i = 0; i < 8; i++) {
                unsigned long long ad;
                PACK2(ad, a[i], a[i]);
#pragma unroll
                for (int j = 0; j < 4; j++) FMA2(acc[i][j], ad, b2[j], acc[i][j]);
            }
        }
        __syncthreads();
    }
#pragma unroll
    for (int i = 0; i < 8; i++)
#pragma unroll
        for (int j = 0; j < 4; j++) {
            float lo, hi;
            UNPACK2(lo, hi, acc[i][j]);
            int n = n0 + tx * 8 + 2 * j;
            size_t base = (size_t)(m0 + ty * 8 + i) * G3 + n;
            g_gi[base] = lo + bih[n];
            g_gi[base + 1] = hi + bih[n + 1];
        }
}

// =============================================================================
// GRU scan: 16-CTA cluster, 512 threads/CTA, persistent over 4096 steps.
//   Protocol identical to R11 (passing): st.shared::cluster + SPLIT
//   barrier.cluster (arrive after stores = release; wait at loop top =
//   acquire).  Issue-count reductions:
//     * h stored PERMUTED+PADDED: h[d] at float slot
//         (d&31)*20 + 2*(d>>6) + ((d>>5)&1)
//       -> consumer lane l reads its 16 k-values (pairs (l+64i, l+64i+32))
//       as 4 x LDS.128 at [l*20 + 4j], feeding FMA2 with zero PACKs.
//       Banks: starts 20l mod 32 cover all 16 even residues x2 -> 4-phase
//       optimal crossbar (same bytes as scalar version).
//     * Row-split reduction (replaces 6 full butterflies; redux.f32 does
//       not exist on sm_103):  weights pre-swapped into Wm (my dim's r/z/n
//       rows) and Wo (partner dim's rows).  Level 0: one shfl_xor(1)
//       exchanges partner-row partials -> 3 rows/lane; then 4 butterfly
//       levels x 3 rows.  42 instr vs 72.
// =============================================================================
__global__ __launch_bounds__(512, 1) void k_gru(const float* __restrict__ Whh,
                                                const float* __restrict__ bhh) {
    __shared__ __align__(16) float h_buf[2][HPAD];
    const int tid = threadIdx.x;
    const int warp = tid >> 5, lane = tid & 31;
    const int q = lane & 1;            // which of the warp's 2 dims is MINE
    const int dstc = lane >> 1;        // destination CTA rank (0..15)
    unsigned int rank;
    asm("mov.u32 %0, %%cluster_ctarank;" : "=r"(rank));

    for (int i = tid; i < 2 * HPAD; i += 512) ((float*)h_buf)[i] = 0.f;

    const int dim_g = (int)rank * 32 + 2 * warp + q;   // my global dim
    // permuted slot for my dim (constant)
    const int pidx = (dim_g & 31) * 20 + 2 * (dim_g >> 6) + ((dim_g >> 5) & 1);

    // Register-resident weights, stride-32 k-permutation:
    // pair i = (k = lane+64i, k = lane+64i+32).
    // Wm[r] = gate r (r,z,n) row of MY dim; Wo[r] = of partner dim.
    unsigned long long Wm[3][8], Wo[3][8];
#pragma unroll
    for (int r = 0; r < 3; r++) {
        const float* wm = Whh + (size_t)(r * HD + (int)rank * 32 + 2 * warp + q) * HD;
        const float* wo = Whh + (size_t)(r * HD + (int)rank * 32 + 2 * warp + (1 - q)) * HD;
#pragma unroll
        for (int i = 0; i < 8; i++) {
            PACK2(Wm[r][i], wm[lane + 64 * i], wm[lane + 64 * i + 32]);
            PACK2(Wo[r][i], wo[lane + 64 * i], wo[lane + 64 * i + 32]);
        }
    }

    // biases for my dim
    const float bh_r = bhh[dim_g];
    const float bh_z = bhh[HD + dim_g];
    const float bh_n = bhh[2 * HD + dim_g];
    float h_reg = 0.f;                 // h_old for my dim

    unsigned int hbase;
    asm("{ .reg .u64 t; cvta.to.shared.u64 t, %1; cvt.u32.u64 %0, t; }"
        : "=r"(hbase) : "l"(&h_buf[0][0]));

    // gi(0) prefetch
    const float* gbase = g_gi + dim_g;
    float gi_r = __ldg(gbase);
    float gi_z = __ldg(gbase + HD);
    float gi_n = __ldg(gbase + 2 * HD);

    __syncthreads();
    asm volatile("barrier.cluster.arrive.aligned;" ::: "memory");

    int p = 0;
    for (int t = 0; t < T_LEN; t++) {
        // acquire h(t): pairs with everyone's arrive from step t-1 (or init)
        asm volatile("barrier.cluster.wait.aligned;" ::: "memory");

        // --- FMA phase: 4 x LDS.128 feed 48 FMA2 directly ---
        unsigned long long am[3], ao[3];
#pragma unroll
        for (int r = 0; r < 3; r++) { am[r] = 0ull; ao[r] = 0ull; }
        const ulonglong2* hp2 = (const ulonglong2*)&h_buf[p][lane * 20];
#pragma unroll
        for (int j = 0; j < 4; j++) {
            ulonglong2 uv = hp2[j];        // pairs i=2j (x) and i=2j+1 (y)
#pragma unroll
            for (int r = 0; r < 3; r++) {
                FMA2(am[r], Wm[r][2 * j],     uv.x, am[r]);
                FMA2(am[r], Wm[r][2 * j + 1], uv.y, am[r]);
                FMA2(ao[r], Wo[r][2 * j],     uv.x, ao[r]);
                FMA2(ao[r], Wo[r][2 * j + 1], uv.y, ao[r]);
            }
        }

        // --- row-split reduction ---
        // level 0: exchange partner-row partials (xor 1)
        float s[3];
#pragma unroll
        for (int r = 0; r < 3; r++) {
            float mlo, mhi, olo, ohi;
            UNPACK2(mlo, mhi, am[r]);
            UNPACK2(olo, ohi, ao[r]);
            s[r] = (mlo + mhi) + __shfl_xor_sync(0xffffffffu, olo + ohi, 1);
        }
        // levels 1..4: butterfly on 3 rows
#pragma unroll
        for (int off = 2; off < 32; off <<= 1)
#pragma unroll
            for (int r = 0; r < 3; r++)
                s[r] += __shfl_xor_sync(0xffffffffu, s[r], off);

        // --- gates for my dim (identical in all 16 lanes of a dim) ---
        float xr = s[0] + gi_r + bh_r;
        float xz = s[1] + gi_z + bh_z;
        float rr = fast_sigmoid(xr);
        float zz = fast_sigmoid(xz);
        float nn = fast_tanh(gi_n + rr * (s[2] + bh_n));
        h_reg = (1.f - zz) * nn + zz * h_reg;

        // --- one DSMEM store per lane: permuted slot -> CTA dstc, buf p^1 ---
        {
            unsigned int dst = hbase + 4u * (unsigned)((p ^ 1) * HPAD + pidx);
            unsigned int rem;
            asm("mapa.shared::cluster.u32 %0, %1, %2;"
                : "=r"(rem) : "r"(dst), "r"(dstc));
            asm volatile("st.shared::cluster.f32 [%0], %1;"
                         :: "r"(rem), "f"(h_reg) : "memory");
        }
        // release our stores for step t
        asm volatile("barrier.cluster.arrive.aligned;" ::: "memory");

        // --- shadow work (overlaps peers reaching the barrier) ---
        if (dstc == 0)                 // one lane per dim writes history
            g_hs[(size_t)t * HD + dim_g] = h_reg;
        {
            const int tn = (t + 1 < T_LEN) ? t + 1 : t;   // in-bounds prefetch
            const float* gp = gbase + (size_t)tn * G3;
            gi_r = __ldg(gp);
            gi_z = __ldg(gp + HD);
            gi_n = __ldg(gp + 2 * HD);
        }
        p ^= 1;
    }
    // final pairing wait: also guarantees no CTA exits while peers could
    // still address its smem
    asm volatile("barrier.cluster.wait.aligned;" ::: "memory");
}

// =============================================================================
// Attention epilogue
// =============================================================================
__global__ void k_logits(const float* __restrict__ watt) {
    const int t = blockIdx.x * 8 + (threadIdx.x >> 5);
    const int lane = threadIdx.x & 31;
    float s = 0.f;
#pragma unroll
    for (int i = 0; i < 16; i++)
        s += g_hs[(size_t)t * HD + lane + 32 * i] * watt[lane + 32 * i];
#pragma unroll
    for (int off = 16; off; off >>= 1) s += __shfl_xor_sync(0xffffffffu, s, off);
    if (lane == 0) g_logits[t] = s;
}

__global__ void k_softmax() {
    __shared__ float red[32];
    __shared__ float bcast;
    const int tid = threadIdx.x, lane = tid & 31, w = tid >> 5;
    float v[4], m = -1e30f;
#pragma unroll
    for (int i = 0; i < 4; i++) {
        v[i] = g_logits[tid + 1024 * i];
        m = fmaxf(m, v[i]);
    }
#pragma unroll
    for (int off = 16; off; off >>= 1)
        m = fmaxf(m, __shfl_xor_sync(0xffffffffu, m, off));
    if (lane == 0) red[w] = m;
    __syncthreads();
    if (w == 0) {
        float x = red[lane];
#pragma unroll
        for (int off = 16; off; off >>= 1)
            x = fmaxf(x, __shfl_xor_sync(0xffffffffu, x, off));
        if (lane == 0) bcast = x;
    }
    __syncthreads();
    const float M = bcast;
    __syncthreads();
    float s = 0.f;
#pragma unroll
    for (int i = 0; i < 4; i++) {
        v[i] = __expf(v[i] - M);
        s += v[i];
    }
#pragma unroll
    for (int off = 16; off; off >>= 1) s += __shfl_xor_sync(0xffffffffu, s, off);
    if (lane == 0) red[w] = s;
    __syncthreads();
    if (w == 0) {
        float x = red[lane];
#pragma unroll
        for (int off = 16; off; off >>= 1) x += __shfl_xor_sync(0xffffffffu, x, off);
        if (lane == 0) bcast = 1.f / x;
    }
    __syncthreads();
    const float inv = bcast;
#pragma unroll
    for (int i = 0; i < 4; i++) g_logits[tid + 1024 * i] = v[i] * inv;
}

__global__ void k_wsum() {
    const int d = threadIdx.x;
    const int b = blockIdx.x;
    float acc = 0.f;
    for (int t = b * 128; t < b * 128 + 128; t++)
        acc += g_logits[t] * g_hs[(size_t)t * HD + d];
    g_part[b * HD + d] = acc;
}

__global__ void k_final(float* __restrict__ out) {
    const int d = threadIdx.x;
    float acc = 0.f;
#pragma unroll
    for (int b = 0; b < 32; b++) acc += g_part[b * HD + d];
    out[d] = acc;
}

// =============================================================================
// Launch
// =============================================================================
extern "C" void kernel_launch(void* const* d_in, const int* in_sizes, int n_in,
                              void* d_out, int out_size) {
    const float* H    = (const float*)d_in[0];
    // d_in[1] = TE (unused)
    const float* Xemb = (const float*)d_in[2];
    const float* Wih  = (const float*)d_in[3];
    const float* Whh  = (const float*)d_in[4];
    const float* bih  = (const float*)d_in[5];
    const float* bhh  = (const float*)d_in[6];
    const float* watt = (const float*)d_in[7];
    float* out = (float*)d_out;

    gemm_visit<<<dim3(4, 32), 256>>>(H, Xemb);
    gemm_gi<<<dim3(12, 32), 256>>>(Wih, bih);

    // 16-CTA cluster GRU scan
    cudaFuncSetAttribute(k_gru, cudaFuncAttributeNonPortableClusterSizeAllowed, 1);
    cudaLaunchConfig_t cfg = {};
    cfg.gridDim = dim3(16, 1, 1);
    cfg.blockDim = dim3(512, 1, 1);
    cfg.dynamicSmemBytes = 0;
    cfg.stream = 0;
    cudaLaunchAttribute attrs[1];
    attrs[0].id = cudaLaunchAttributeClusterDimension;
    attrs[0].val.clusterDim.x = 16;
    attrs[0].val.clusterDim.y = 1;
    attrs[0].val.clusterDim.z = 1;
    cfg.attrs = attrs;
    cfg.numAttrs = 1;
    cudaLaunchKernelEx(&cfg, k_gru, Whh, bhh);

    k_logits<<<512, 256>>>(watt);
    k_softmax<<<1, 1024>>>();
    k_wsum<<<32, 512>>>();
    k_final<<<1, 512>>>(out);
}